// round 7
// baseline (speedup 1.0000x reference)
#include <cuda_runtime.h>
#include <cstdint>

#define NN 20000
#define NE 320000
#define NG 512

// ---------------- scratch (device globals; no allocation allowed) ----------
__device__ float g_bufA[NN * 1024];
__device__ float g_bufB[NN * 1024];
__device__ float g_deg[NN];
__device__ float g_dinv[NN];
__device__ float g_enorm[NE];
__device__ float g_ps[1024];
__device__ float g_pq[1024];
__device__ float g_aA[5 * 1024];
__device__ float g_aD[5 * 1024];
__device__ float g_gate[NN];
__device__ float g_gmax[NG];
__device__ float g_gsum[NG];
__device__ float g_pool[NG * 1024];
__device__ float g_p2[NG * 128];
__device__ float g_p3[NG * 16];

// ---------------- small utility kernels ------------------------------------
__global__ void k_fill(float* p, long n, float v) {
    long i = (long)blockIdx.x * blockDim.x + threadIdx.x;
    if (i < n) p[i] = v;
}

__global__ void k_deg(const int* __restrict__ col, float* __restrict__ deg) {
    int e = blockIdx.x * blockDim.x + threadIdx.x;
    if (e < NE) atomicAdd(&deg[col[e]], 1.0f);
}

__global__ void k_dinv(const float* __restrict__ deg, float* __restrict__ dinv) {
    int i = blockIdx.x * blockDim.x + threadIdx.x;
    if (i < NN) dinv[i] = rsqrtf(deg[i]);
}

__global__ void k_enorm(const int* __restrict__ row, const int* __restrict__ col,
                        const float* __restrict__ dinv, float* __restrict__ nrm) {
    int e = blockIdx.x * blockDim.x + threadIdx.x;
    if (e < NE) nrm[e] = dinv[row[e]] * dinv[col[e]];
}

// ---------------- aggregation: dst = D^-1/2 (A+I) D^-1/2 @ f(src) ----------
// f(x)_c = inA_c * x_c + inD_c (pending BN affine) or identity.
// self-loop term doubles as the initializer for dst
__global__ void k_aggself(const float* __restrict__ src, float* __restrict__ dst,
                          const float* __restrict__ dinv,
                          const float* __restrict__ inA, const float* __restrict__ inD,
                          long tot, int F) {
    long i = (long)blockIdx.x * blockDim.x + threadIdx.x;
    if (i >= tot) return;
    int v = (int)(i / F);
    int c = (int)(i - (long)v * F);
    float x = src[i];
    if (inA) x = fmaf(inA[c], x, inD[c]);
    float d = dinv[v];
    dst[i] = d * d * x;
}

// warp per edge, 8 edges per 256-thread block; fire-and-forget RED.ADD
__global__ void k_aggedge(const float* __restrict__ src, float* __restrict__ dst,
                          const int* __restrict__ row, const int* __restrict__ col,
                          const float* __restrict__ nrm,
                          const float* __restrict__ inA, const float* __restrict__ inD,
                          int F) {
    int e = blockIdx.x * 8 + (threadIdx.x >> 5);
    if (e >= NE) return;
    int lane = threadIdx.x & 31;
    float w = nrm[e];
    const float* s = src + (long)row[e] * F;
    float* d = dst + (long)col[e] * F;
    if (inA) {
        for (int f = lane; f < F; f += 32)
            atomicAdd(&d[f], w * fmaf(inA[f], s[f], inD[f]));
    } else {
        for (int f = lane; f < F; f += 32)
            atomicAdd(&d[f], w * s[f]);
    }
}

// post pass for agg-last layers: X = relu(X + bias), accumulate column stats
__global__ void k_post(float* __restrict__ X, const float* __restrict__ bias,
                       float* __restrict__ ps, float* __restrict__ pq, int F) {
    int lane = threadIdx.x & 31, ry = threadIdx.x >> 5;   // 256 = 8x32
    int c = blockIdx.x * 32 + lane;
    int nch = gridDim.y;
    int per = (NN + nch - 1) / nch;
    int r0 = blockIdx.y * per, r1 = min(NN, r0 + per);
    float s = 0.0f, q = 0.0f;
    if (c < F) {
        float bb = bias[c];
        for (int r = r0 + ry; r < r1; r += 8) {
            float v = fmaxf(X[(long)r * F + c] + bb, 0.0f);
            X[(long)r * F + c] = v;
            s += v;
            q += v * v;
        }
    }
    __shared__ float sh[16][32];
    sh[ry][lane] = s;
    sh[8 + ry][lane] = q;
    __syncthreads();
    if (ry == 0 && c < F) {
#pragma unroll
        for (int i = 1; i < 8; i++) { s += sh[i][lane]; q += sh[8 + i][lane]; }
        atomicAdd(&ps[c], s);
        atomicAdd(&pq[c], q);
    }
}

// ---------------- 3xTF32 tensor-core GEMM ----------------------------------
// C = f(A) @ W (+bias, relu), f = pending BN affine on A's columns (or id).
// Optional per-output-column sum/sumsq stats for the next BN.
__device__ __forceinline__ void tf32split(float x, uint32_t& hi, uint32_t& lo) {
    uint32_t h;
    asm("cvt.rna.tf32.f32 %0, %1;" : "=r"(h) : "f"(x));
    float r = x - __uint_as_float(h);
    uint32_t l;
    asm("cvt.rna.tf32.f32 %0, %1;" : "=r"(l) : "f"(r));
    hi = h;
    lo = l;
}

__device__ __forceinline__ void mma_tf32(float* d, const uint32_t* a, const uint32_t* b) {
    asm volatile(
        "mma.sync.aligned.m16n8k8.row.col.f32.tf32.tf32.f32 "
        "{%0,%1,%2,%3}, {%4,%5,%6,%7}, {%8,%9}, {%0,%1,%2,%3};"
        : "+f"(d[0]), "+f"(d[1]), "+f"(d[2]), "+f"(d[3])
        : "r"(a[0]), "r"(a[1]), "r"(a[2]), "r"(a[3]), "r"(b[0]), "r"(b[1]));
}

__global__ __launch_bounds__(256) void k_gemm_tf32x3(
    const float* __restrict__ A, const float* __restrict__ W,
    const float* __restrict__ bias, float* __restrict__ C,
    const float* __restrict__ inA, const float* __restrict__ inD,
    float* __restrict__ ps, float* __restrict__ pq,
    int M, int N, int K, int doRelu)
{
    __shared__ float As[2][16][132];
    __shared__ float Bs[2][16][132];
    __shared__ float s_sum[128], s_sq[128];
    const int tid = threadIdx.x;
    const int warp = tid >> 5, lane = tid & 31;
    const int wm = warp >> 2, wn = warp & 3;
    const int gr = lane >> 2, gk = lane & 3;
    const int bm = blockIdx.y * 128, bn = blockIdx.x * 128;

    float acc[4][4][4];
#pragma unroll
    for (int i = 0; i < 4; i++)
#pragma unroll
        for (int j = 0; j < 4; j++)
#pragma unroll
            for (int r = 0; r < 4; r++) acc[i][j][r] = 0.0f;

    const int nc = (K + 15) / 16;
    const bool vec = (K & 15) == 0;

    const int ar = tid >> 2, aq = tid & 3;
    const int wr = tid >> 5, wc = (tid & 31) * 4;

    float ra[8];
    float rb[8];

    auto fetch = [&](int c) {
        int k0 = c * 16;
        if (vec) {
            int g0 = bm + ar, g1 = bm + ar + 64;
            if (g0 < M) {
                float4 v = *(const float4*)(A + (long)g0 * K + k0 + aq * 4);
                ra[0] = v.x; ra[1] = v.y; ra[2] = v.z; ra[3] = v.w;
            } else ra[0] = ra[1] = ra[2] = ra[3] = 0.0f;
            if (g1 < M) {
                float4 v = *(const float4*)(A + (long)g1 * K + k0 + aq * 4);
                ra[4] = v.x; ra[5] = v.y; ra[6] = v.z; ra[7] = v.w;
            } else ra[4] = ra[5] = ra[6] = ra[7] = 0.0f;
            if (inA) {
                float4 av = *(const float4*)(inA + k0 + aq * 4);
                float4 dv = *(const float4*)(inD + k0 + aq * 4);
                ra[0] = fmaf(av.x, ra[0], dv.x); ra[1] = fmaf(av.y, ra[1], dv.y);
                ra[2] = fmaf(av.z, ra[2], dv.z); ra[3] = fmaf(av.w, ra[3], dv.w);
                ra[4] = fmaf(av.x, ra[4], dv.x); ra[5] = fmaf(av.y, ra[5], dv.y);
                ra[6] = fmaf(av.z, ra[6], dv.z); ra[7] = fmaf(av.w, ra[7], dv.w);
            }
        } else {
#pragma unroll
            for (int h = 0; h < 2; h++) {
                int g = bm + ar + h * 64;
#pragma unroll
                for (int q = 0; q < 4; q++) {
                    int kk = k0 + aq * 4 + q;
                    float x = (g < M && kk < K) ? A[(long)g * K + kk] : 0.0f;
                    if (inA && kk < K) x = fmaf(inA[kk], x, inD[kk]);
                    ra[h * 4 + q] = x;
                }
            }
        }
#pragma unroll
        for (int h = 0; h < 2; h++) {
            int kk = k0 + wr + h * 8;
            if (kk < K) {
                float4 v = *(const float4*)(W + (long)kk * N + bn + wc);
                rb[h * 4 + 0] = v.x; rb[h * 4 + 1] = v.y;
                rb[h * 4 + 2] = v.z; rb[h * 4 + 3] = v.w;
            } else rb[h * 4 + 0] = rb[h * 4 + 1] = rb[h * 4 + 2] = rb[h * 4 + 3] = 0.0f;
        }
    };
    auto stage = [&](int buf) {
#pragma unroll
        for (int h = 0; h < 2; h++)
#pragma unroll
            for (int q = 0; q < 4; q++)
                As[buf][aq * 4 + q][ar + h * 64] = ra[h * 4 + q];
#pragma unroll
        for (int h = 0; h < 2; h++) {
            float* p = &Bs[buf][wr + h * 8][wc];
            p[0] = rb[h * 4 + 0];
            p[1] = rb[h * 4 + 1];
            p[2] = rb[h * 4 + 2];
            p[3] = rb[h * 4 + 3];
        }
    };

    fetch(0);
    stage(0);
    __syncthreads();

    for (int c = 0; c < nc; c++) {
        int buf = c & 1;
        if (c + 1 < nc) fetch(c + 1);
#pragma unroll
        for (int kk = 0; kk < 2; kk++) {
            uint32_t ah[4][4], al[4][4], bh[4][2], bl[4][2];
#pragma unroll
            for (int i = 0; i < 4; i++) {
                int m = wm * 64 + i * 16 + gr;
                tf32split(As[buf][kk * 8 + gk][m],      ah[i][0], al[i][0]);
                tf32split(As[buf][kk * 8 + gk][m + 8],  ah[i][1], al[i][1]);
                tf32split(As[buf][kk * 8 + gk + 4][m],      ah[i][2], al[i][2]);
                tf32split(As[buf][kk * 8 + gk + 4][m + 8],  ah[i][3], al[i][3]);
            }
#pragma unroll
            for (int j = 0; j < 4; j++) {
                int n = wn * 32 + j * 8 + gr;
                tf32split(Bs[buf][kk * 8 + gk][n],     bh[j][0], bl[j][0]);
                tf32split(Bs[buf][kk * 8 + gk + 4][n], bh[j][1], bl[j][1]);
            }
#pragma unroll
            for (int i = 0; i < 4; i++)
#pragma unroll
                for (int j = 0; j < 4; j++) {
                    mma_tf32(acc[i][j], al[i], bh[j]);   // lo*hi
                    mma_tf32(acc[i][j], ah[i], bl[j]);   // hi*lo
                    mma_tf32(acc[i][j], ah[i], bh[j]);   // hi*hi
                }
        }
        if (c + 1 < nc) {
            stage((c + 1) & 1);
        }
        __syncthreads();
    }

    // epilogue (+ optional column stats)
    float csum[8], csq[8];
#pragma unroll
    for (int t = 0; t < 8; t++) { csum[t] = 0.0f; csq[t] = 0.0f; }
#pragma unroll
    for (int i = 0; i < 4; i++) {
        int r0 = bm + wm * 64 + i * 16 + gr;
        int r1 = r0 + 8;
#pragma unroll
        for (int j = 0; j < 4; j++) {
            int cc = bn + wn * 32 + j * 8 + gk * 2;
            float b0 = bias ? bias[cc] : 0.0f;
            float b1 = bias ? bias[cc + 1] : 0.0f;
            float v0 = acc[i][j][0] + b0, v1 = acc[i][j][1] + b1;
            float v2 = acc[i][j][2] + b0, v3 = acc[i][j][3] + b1;
            if (doRelu) {
                v0 = fmaxf(v0, 0.0f); v1 = fmaxf(v1, 0.0f);
                v2 = fmaxf(v2, 0.0f); v3 = fmaxf(v3, 0.0f);
            }
            if (r0 < M) {
                *(float2*)(C + (long)r0 * N + cc) = make_float2(v0, v1);
                csum[j * 2] += v0; csq[j * 2] += v0 * v0;
                csum[j * 2 + 1] += v1; csq[j * 2 + 1] += v1 * v1;
            }
            if (r1 < M) {
                *(float2*)(C + (long)r1 * N + cc) = make_float2(v2, v3);
                csum[j * 2] += v2; csq[j * 2] += v2 * v2;
                csum[j * 2 + 1] += v3; csq[j * 2 + 1] += v3 * v3;
            }
        }
    }
    if (ps) {
        if (tid < 128) { s_sum[tid] = 0.0f; s_sq[tid] = 0.0f; }
        __syncthreads();
#pragma unroll
        for (int j = 0; j < 4; j++) {
            int cl = wn * 32 + j * 8 + gk * 2;
            atomicAdd(&s_sum[cl], csum[j * 2]);
            atomicAdd(&s_sq[cl], csq[j * 2]);
            atomicAdd(&s_sum[cl + 1], csum[j * 2 + 1]);
            atomicAdd(&s_sq[cl + 1], csq[j * 2 + 1]);
        }
        __syncthreads();
        if (tid < 128) {
            atomicAdd(&ps[bn + tid], s_sum[tid]);
            atomicAdd(&pq[bn + tid], s_sq[tid]);
        }
    }
}

// ---------------- BN finalize: stats -> per-feature affine ------------------
__global__ void k_bnfin(const float* __restrict__ ps, const float* __restrict__ pq,
                        const float* __restrict__ gm, const float* __restrict__ bt,
                        float* __restrict__ aA, float* __restrict__ aD, int F) {
    int c = blockIdx.x * blockDim.x + threadIdx.x;
    if (c >= F) return;
    float m = ps[c] / (float)NN;
    float var = pq[c] / (float)NN - m * m;
    float rstd = rsqrtf(fmaxf(var, 0.0f) + 1e-5f);
    float a = gm[c] * rstd;
    aA[c] = a;
    aD[c] = bt[c] - a * m;
}

// ---------------- global attention pooling (with pending affine) ------------
__global__ void k_gate(const float* __restrict__ H, const float* __restrict__ Wg,
                       const float* __restrict__ bg, const float* __restrict__ aA,
                       const float* __restrict__ aD, float* __restrict__ gate) {
    int t = blockIdx.x * blockDim.x + threadIdx.x;
    int v = t >> 5, lane = t & 31;
    if (v >= NN) return;
    const float* h = H + (long)v * 1024;
    float s = 0.0f;
    for (int k = lane; k < 1024; k += 32)
        s += fmaf(aA[k], h[k], aD[k]) * Wg[k];
#pragma unroll
    for (int o = 16; o; o >>= 1) s += __shfl_down_sync(0xffffffffu, s, o);
    if (lane == 0) gate[v] = s + bg[0];
}

__global__ void k_segmax(const float* __restrict__ gate, const int* __restrict__ batch,
                         float* __restrict__ gmax) {
    int i = blockIdx.x * blockDim.x + threadIdx.x;
    if (i >= NN) return;
    float v = gate[i];
    float* addr = &gmax[batch[i]];
    int old = __float_as_int(*addr);
    while (v > __int_as_float(old)) {
        int prev = atomicCAS((int*)addr, old, __float_as_int(v));
        if (prev == old) break;
        old = prev;
    }
}

__global__ void k_exps(float* __restrict__ gate, const int* __restrict__ batch,
                       const float* __restrict__ gmax, float* __restrict__ gsum) {
    int i = blockIdx.x * blockDim.x + threadIdx.x;
    if (i >= NN) return;
    int b = batch[i];
    float e = expf(gate[i] - gmax[b]);
    gate[i] = e;
    atomicAdd(&gsum[b], e);
}

__global__ void k_coef(float* __restrict__ gate, const int* __restrict__ batch,
                       const float* __restrict__ gsum) {
    int i = blockIdx.x * blockDim.x + threadIdx.x;
    if (i >= NN) return;
    gate[i] = gate[i] / gsum[batch[i]];
}

__global__ void k_pool(const float* __restrict__ H, const float* __restrict__ gate,
                       const int* __restrict__ batch, const float* __restrict__ aA,
                       const float* __restrict__ aD, float* __restrict__ pool) {
    long i = (long)blockIdx.x * blockDim.x + threadIdx.x;
    if (i >= (long)NN * 1024) return;
    int v = (int)(i >> 10);
    int f = (int)(i & 1023);
    float val = fmaf(aA[f], H[i], aD[f]);
    atomicAdd(&pool[((long)batch[v] << 10) + f], gate[v] * val);
}

// ---------------- small MLP GEMMs ------------------------------------------
__global__ void k_mlp(const float* __restrict__ X, const float* __restrict__ W,
                      const float* __restrict__ bias, float* __restrict__ Y,
                      int M, int N, int K, int relu) {
    int i = blockIdx.x * blockDim.x + threadIdx.x;
    if (i >= M * N) return;
    int m = i / N, n = i % N;
    float s = bias[n];
    for (int k = 0; k < K; k++) s += X[m * K + k] * W[k * N + n];
    if (relu) s = fmaxf(s, 0.0f);
    Y[i] = s;
}

// ---------------- launch -----------------------------------------------------
extern "C" void kernel_launch(void* const* d_in, const int* in_sizes, int n_in,
                              void* d_out, int out_size) {
    (void)in_sizes; (void)n_in; (void)out_size;
    const float* x = (const float*)d_in[0];
    const int* ei = (const int*)d_in[1];
    const int* row = ei;
    const int* col = ei + NE;
    const int* batch = (const int*)d_in[2];
    const float *W[5], *b[5], *g[5], *be[5];
    for (int i = 0; i < 5; i++) {
        W[i]  = (const float*)d_in[3 + 4 * i];
        b[i]  = (const float*)d_in[4 + 4 * i];
        g[i]  = (const float*)d_in[5 + 4 * i];
        be[i] = (const float*)d_in[6 + 4 * i];
    }
    const float* Wg  = (const float*)d_in[23];
    const float* bg  = (const float*)d_in[24];
    const float* Wf2 = (const float*)d_in[25];
    const float* bf2 = (const float*)d_in[26];
    const float* Wf3 = (const float*)d_in[27];
    const float* bf3 = (const float*)d_in[28];
    const float* Wf4 = (const float*)d_in[29];
    const float* bf4 = (const float*)d_in[30];

    float *A, *B, *deg, *dinv, *nrm, *ps, *pq, *aA, *aD;
    float *gate, *gmax, *gsum, *pool, *p2, *p3;
    cudaGetSymbolAddress((void**)&A, g_bufA);
    cudaGetSymbolAddress((void**)&B, g_bufB);
    cudaGetSymbolAddress((void**)&deg, g_deg);
    cudaGetSymbolAddress((void**)&dinv, g_dinv);
    cudaGetSymbolAddress((void**)&nrm, g_enorm);
    cudaGetSymbolAddress((void**)&ps, g_ps);
    cudaGetSymbolAddress((void**)&pq, g_pq);
    cudaGetSymbolAddress((void**)&aA, g_aA);
    cudaGetSymbolAddress((void**)&aD, g_aD);
    cudaGetSymbolAddress((void**)&gate, g_gate);
    cudaGetSymbolAddress((void**)&gmax, g_gmax);
    cudaGetSymbolAddress((void**)&gsum, g_gsum);
    cudaGetSymbolAddress((void**)&pool, g_pool);
    cudaGetSymbolAddress((void**)&p2, g_p2);
    cudaGetSymbolAddress((void**)&p3, g_p3);

    // ---- graph normalization (depends only on edge_index) ----
    k_fill<<<(NN + 255) / 256, 256>>>(deg, NN, 1.0f);            // self-loop
    k_deg<<<(NE + 255) / 256, 256>>>(col, deg);
    k_dinv<<<(NN + 255) / 256, 256>>>(deg, dinv);
    k_enorm<<<(NE + 255) / 256, 256>>>(row, col, dinv, nrm);

    auto agg = [&](const float* src, float* dst, int F, const float* iA, const float* iD) {
        long tot = (long)NN * F;
        k_aggself<<<(int)((tot + 255) / 256), 256>>>(src, dst, dinv, iA, iD, tot, F);
        k_aggedge<<<(NE + 7) / 8, 256>>>(src, dst, row, col, nrm, iA, iD, F);
    };
    auto gemm = [&](const float* Ain, const float* Win, const float* bias, float* C,
                    const float* iA, const float* iD, bool stats,
                    int M, int Nn, int K, int relu) {
        dim3 gr(Nn / 128, (M + 127) / 128);
        k_gemm_tf32x3<<<gr, 256>>>(Ain, Win, bias, C, iA, iD,
                                   stats ? ps : nullptr, stats ? pq : nullptr,
                                   M, Nn, K, relu);
    };
    auto zstat = [&](int F) {
        k_fill<<<(F + 255) / 256, 256>>>(ps, F, 0.0f);
        k_fill<<<(F + 255) / 256, 256>>>(pq, F, 0.0f);
    };
    auto post = [&](float* X, const float* bias, int F) {
        dim3 gr((F + 31) / 32, 20);
        k_post<<<gr, 256>>>(X, bias, ps, pq, F);
    };
    auto bnfin = [&](int layer, int F) {
        k_bnfin<<<(F + 127) / 128, 128>>>(ps, pq, g[layer], be[layer],
                                          aA + layer * 1024, aD + layer * 1024, F);
    };

    // Layer 1 (29 -> 1024): agg(x) -> A; gemm(+b1,relu,stats) -> B = X1
    agg(x, A, 29, nullptr, nullptr);
    zstat(1024);
    gemm(A, W[0], b[0], B, nullptr, nullptr, true, NN, 1024, 29, 1);
    bnfin(0, 1024);

    // Layer 2 (1024 -> 512): gemm(affine1 on A-load) -> A; agg -> B; post(+b2,relu,stats)
    gemm(B, W[1], nullptr, A, aA + 0, aD + 0, false, NN, 512, 1024, 0);
    agg(A, B, 512, nullptr, nullptr);
    zstat(512);
    post(B, b[1], 512);
    bnfin(1, 512);

    // Layer 3 (512 -> 256): gemm(affine2) -> A; agg -> B; post(+b3,relu,stats)
    gemm(B, W[2], nullptr, A, aA + 1024, aD + 1024, false, NN, 256, 512, 0);
    agg(A, B, 256, nullptr, nullptr);
    zstat(256);
    post(B, b[2], 256);
    bnfin(2, 256);

    // Layer 4 (256 -> 512): agg(affine3 on src) -> A; gemm(+b4,relu,stats) -> B = X4
    agg(B, A, 256, aA + 2048, aD + 2048);
    zstat(512);
    gemm(A, W[3], b[3], B, nullptr, nullptr, true, NN, 512, 256, 1);
    bnfin(3, 512);

    // Layer 5 (512 -> 1024): agg(affine4) -> A; gemm(+b5,relu,stats) -> B = X5
    agg(B, A, 512, aA + 3072, aD + 3072);
    zstat(1024);
    gemm(A, W[4], b[4], B, nullptr, nullptr, true, NN, 1024, 512, 1);
    bnfin(4, 1024);

    // ---- global attention pooling (affine5 applied on the fly) ----
    const float* a5A = aA + 4096;
    const float* a5D = aD + 4096;
    k_gate<<<(NN * 32 + 255) / 256, 256>>>(B, Wg, bg, a5A, a5D, gate);
    k_fill<<<(NG + 255) / 256, 256>>>(gmax, NG, -3e38f);
    k_fill<<<(NG + 255) / 256, 256>>>(gsum, NG, 0.0f);
    k_segmax<<<(NN + 255) / 256, 256>>>(gate, batch, gmax);
    k_exps<<<(NN + 255) / 256, 256>>>(gate, batch, gmax, gsum);
    k_coef<<<(NN + 255) / 256, 256>>>(gate, batch, gsum);
    k_fill<<<(NG * 1024 + 255) / 256, 256>>>(pool, (long)NG * 1024, 0.0f);
    k_pool<<<(int)(((long)NN * 1024 + 255) / 256), 256>>>(B, gate, batch, a5A, a5D, pool);

    // ---- MLP head ----
    k_mlp<<<(NG * 128 + 255) / 256, 256>>>(pool, Wf2, bf2, p2, NG, 128, 1024, 1);
    k_mlp<<<(NG * 16 + 255) / 256, 256>>>(p2, Wf3, bf3, p3, NG, 16, 128, 1);
    k_mlp<<<(NG + 255) / 256, 256>>>(p3, Wf4, bf4, (float*)d_out, NG, 1, 16, 0);
}